// round 1
// baseline (speedup 1.0000x reference)
#include <cuda_runtime.h>

#define NN 16384
#define HH 4
#define DD 64
#define BB 512
#define KK 8
#define NQ (2*BB)   // 1024 queries: [src(0..B-1), dst(B..2B-1)] == edges flat
#define QT 16       // queries per block in knn kernel
#define CT 64       // candidate tile
#define CST 68      // smem row stride (floats), padded, multiple of 4

__device__ float g_pn2[HH*NN];
__device__ int   g_knn[NQ*HH*KK];

// ---------------------------------------------------------------- kernel 1
__global__ __launch_bounds__(256) void pn2_kernel(const float* __restrict__ pos) {
    int id = blockIdx.x*256 + threadIdx.x;   // 0 .. NN*HH-1
    int n = id >> 2, h = id & 3;
    const float4* p = (const float4*)(pos + ((size_t)n*HH + h)*DD);
    float s = 0.f;
#pragma unroll
    for (int i = 0; i < DD/4; i++) {
        float4 v = p[i];
        s += v.x*v.x + v.y*v.y + v.z*v.z + v.w*v.w;
    }
    g_pn2[h*NN + n] = s;
}

__device__ __forceinline__ bool better(float av, int ai, float bv, int bi) {
    // smaller value wins; tie -> smaller index (matches jax top_k stability)
    return av < bv || (av == bv && ai < bi);
}

// ---------------------------------------------------------------- kernel 2
// grid: (NQ/QT, HH), block: 256 threads = 16 query-groups x 16 lanes.
// Each thread: full query vector in registers, 4 candidates per 64-wide tile,
// register-resident sorted top-9 (score, idx), then 16-lane shfl merge.
__global__ __launch_bounds__(256, 2) void knn_kernel(const float* __restrict__ pos,
                                                     const int* __restrict__ edges) {
    __shared__ __align__(16) float s_cand[DD*CST];   // [d][c], stride CST
    __shared__ float s_pn2[CT];

    const int h = blockIdx.y;
    const int t = threadIdx.x;
    const int g = t >> 4;          // query group 0..15
    const int l = t & 15;          // lane within group
    const int q = blockIdx.x * QT + g;
    const int node = edges[q];     // q<B -> src[q], else dst[q-B] (flat layout)

    float qreg[DD];
    {
        const float4* qp = (const float4*)(pos + ((size_t)node*HH + h)*DD);
#pragma unroll
        for (int i = 0; i < DD/4; i++) {
            float4 v = qp[i];
            qreg[4*i+0] = v.x; qreg[4*i+1] = v.y;
            qreg[4*i+2] = v.z; qreg[4*i+3] = v.w;
        }
    }

    const float INF = __int_as_float(0x7f800000);
    float lv[KK+1]; int li[KK+1];
#pragma unroll
    for (int i = 0; i <= KK; i++) { lv[i] = INF; li[i] = 0x7fffffff; }

    const int f  = t & 15;   // float4 index within a candidate row
    const int cb = t >> 4;   // candidate sub-index for staging

    for (int n0 = 0; n0 < NN; n0 += CT) {
        // ---- stage tile (transposed [d][c]) ----
#pragma unroll
        for (int r = 0; r < 4; r++) {
            int c = r*16 + cb;
            float4 v = ((const float4*)(pos + ((size_t)(n0+c)*HH + h)*DD))[f];
            int d = 4*f;
            s_cand[(d+0)*CST + c] = v.x;
            s_cand[(d+1)*CST + c] = v.y;
            s_cand[(d+2)*CST + c] = v.z;
            s_cand[(d+3)*CST + c] = v.w;
        }
        if (t < CT) s_pn2[t] = g_pn2[h*NN + n0 + t];
        __syncthreads();

        // ---- 4 dot products ----
        float a0=0.f, a1=0.f, a2=0.f, a3=0.f;
#pragma unroll
        for (int d = 0; d < DD; d++) {
            float4 cv = *(const float4*)&s_cand[d*CST + 4*l];
            float qv = qreg[d];
            a0 += qv*cv.x; a1 += qv*cv.y; a2 += qv*cv.z; a3 += qv*cv.w;
        }
        float vv0 = s_pn2[4*l+0] - 2.f*a0;
        float vv1 = s_pn2[4*l+1] - 2.f*a1;
        float vv2 = s_pn2[4*l+2] - 2.f*a2;
        float vv3 = s_pn2[4*l+3] - 2.f*a3;
        float vv[4] = {vv0, vv1, vv2, vv3};

        // ---- top-9 insertion ----
#pragma unroll
        for (int j = 0; j < 4; j++) {
            float v = vv[j]; int idx = n0 + 4*l + j;
            if (better(v, idx, lv[KK], li[KK])) {
                lv[KK] = v; li[KK] = idx;
#pragma unroll
                for (int i = KK; i > 0; i--) {
                    if (better(lv[i], li[i], lv[i-1], li[i-1])) {
                        float tv = lv[i]; lv[i] = lv[i-1]; lv[i-1] = tv;
                        int   ti = li[i]; li[i] = li[i-1]; li[i-1] = ti;
                    }
                }
            }
        }
        __syncthreads();
    }

    // ---- merge 16 sorted lists within the query group (shfl over 16 lanes) ----
    int res[KK];
    for (int r = 0; r <= KK; r++) {
        float v = lv[0]; int i = li[0];
        float bv = v;    int bi = i;
#pragma unroll
        for (int o = 1; o < 16; o <<= 1) {
            float ov = __shfl_xor_sync(0xffffffffu, bv, o);
            int   oi = __shfl_xor_sync(0xffffffffu, bi, o);
            if (better(ov, oi, bv, bi)) { bv = ov; bi = oi; }
        }
        if (v == bv && i == bi) {  // this lane's head won: pop it
#pragma unroll
            for (int j = 0; j < KK; j++) { lv[j] = lv[j+1]; li[j] = li[j+1]; }
            lv[KK] = __int_as_float(0x7f800000); li[KK] = 0x7fffffff;
        }
        if (r >= 1) res[r-1] = bi;    // rank 0 == self, dropped
    }
    if (l == 0) {
#pragma unroll
        for (int k = 0; k < KK; k++) g_knn[(q*HH + h)*KK + k] = res[k];
    }
}

// ---------------------------------------------------------------- kernel 3
// One block per edge b; 64 threads = 2 sides x 4 heads x 8 neighbors.
__global__ __launch_bounds__(64) void epi_kernel(const float* __restrict__ pos,
                                                 const float* __restrict__ grads,
                                                 const float* __restrict__ adj,
                                                 const float* __restrict__ lw,
                                                 const int* __restrict__ edges,
                                                 float* __restrict__ out) {
    __shared__ float sd[HH*16];
    __shared__ float sl[HH*16];
    __shared__ float sh[HH];

    int b = blockIdx.x, t = threadIdx.x;
    int side = t >> 5;          // 0: src side, 1: dst side
    int h = (t >> 3) & 3;
    int k = t & 7;

    int sb = edges[b], db = edges[BB + b];
    int qn = side ? db : sb;            // query node
    int gn = side ? sb : db;            // grads node (crossed)
    int q  = side ? (BB + b) : b;
    int nb = g_knn[(q*HH + h)*KK + k];  // neighbor node

    const float4* qp = (const float4*)(pos   + ((size_t)qn*HH + h)*DD);
    const float4* np = (const float4*)(pos   + ((size_t)nb*HH + h)*DD);
    const float4* gp = (const float4*)(grads + ((size_t)gn*HH + h)*DD);

    float ss = 0.f, cc = 0.f;
#pragma unroll
    for (int i = 0; i < DD/4; i++) {
        float4 a = qp[i], c = np[i], g4 = gp[i];
        float d0 = a.x - c.x, d1 = a.y - c.y, d2 = a.z - c.z, d3 = a.w - c.w;
        ss += d0*d0 + d1*d1 + d2*d2 + d3*d3;
        cc += d0*g4.x + d1*g4.y + d2*g4.z + d3*g4.w;
    }
    float dist = sqrtf(ss);
    // src side: adj[neighbor, dst]; dst side: adj[src, neighbor]
    float adjv = side ? adj[(size_t)sb*NN + nb] : adj[(size_t)nb*NN + db];
    float logit = lw[0]*adjv + cc;

    int slot = h*16 + side*8 + k;
    sd[slot] = dist;
    sl[slot] = logit;
    __syncthreads();

    if (t < HH) {
        float mind = 1.0f;  // sentinel distance
#pragma unroll
        for (int j = 0; j < 16; j++) mind = fminf(mind, sd[t*16 + j]);
        float num = 0.f;
        float den = 8.f * expf(mind - 1.0f);  // 8 sentinels, logit 0
#pragma unroll
        for (int j = 0; j < 16; j++) {
            float e = expf(mind - sd[t*16 + j]);
            den += e;
            num += e * sl[t*16 + j];
        }
        sh[t] = num / den;
    }
    __syncthreads();
    if (t == 0) {
        float s = 0.25f * (sh[0] + sh[1] + sh[2] + sh[3]);
        out[b] = 1.f / (1.f + expf(-s));
    }
}

// ---------------------------------------------------------------- launch
extern "C" void kernel_launch(void* const* d_in, const int* in_sizes, int n_in,
                              void* d_out, int out_size) {
    const float* pos   = (const float*)d_in[0];
    const float* grads = (const float*)d_in[1];
    const float* adj   = (const float*)d_in[2];
    const float* lw    = (const float*)d_in[3];
    const int*   edges = (const int*)  d_in[4];
    float* out = (float*)d_out;

    pn2_kernel<<<(NN*HH)/256, 256>>>(pos);
    knn_kernel<<<dim3(NQ/QT, HH), 256>>>(pos, edges);
    epi_kernel<<<BB, 64>>>(pos, grads, adj, lw, edges, out);
}

// round 2
// speedup vs baseline: 1.6157x; 1.6157x over previous
#include <cuda_runtime.h>

#define NN 16384
#define HH 4
#define DD 64
#define BB 512
#define KK 8
#define NQ (2*BB)      // queries: edges flat [src(0..B-1), dst(B..2B-1)]
#define QB 32          // queries per block (16 pairs)
#define CT 128         // candidates per tile
#define NPART 2        // candidate-space partitions
#define SPAN (NN/NPART)
#define PST 68         // smem row stride in floats (candidate-major)

typedef unsigned long long ull;

__device__ float g_pn2[HH*NN];
__device__ int   g_knn[NQ*HH*KK];
__device__ float g_pv[NPART*NQ*HH*(KK+1)];
__device__ int   g_pi[NPART*NQ*HH*(KK+1)];

#define FMA2(acc, a, b) asm("fma.rn.f32x2 %0, %1, %2, %0;" : "+l"(acc) : "l"(a), "l"(b))

__device__ __forceinline__ bool better(float av, int ai, float bv, int bi) {
    return av < bv || (av == bv && ai < bi);
}

// ---------------------------------------------------------------- kernel 1
__global__ __launch_bounds__(256) void pn2_kernel(const float* __restrict__ pos) {
    int id = blockIdx.x*256 + threadIdx.x;
    int n = id >> 2, h = id & 3;
    const float4* p = (const float4*)(pos + ((size_t)n*HH + h)*DD);
    float s = 0.f;
#pragma unroll
    for (int i = 0; i < DD/4; i++) {
        float4 v = p[i];
        s += v.x*v.x + v.y*v.y + v.z*v.z + v.w*v.w;
    }
    g_pn2[h*NN + n] = s;
}

// ---------------------------------------------------------------- kernel 2
// grid (NQ/QB, HH, NPART), 256 threads.
// thread: lane = t&15 (candidates lane+16j, j<8), qpair = t>>4 (queries 2qp, 2qp+1).
// f32x2 accumulators over d-lane pairs; per-thread sorted top-9 per query;
// 16-lane shfl merge; partial top-9 written per partition.
__global__ __launch_bounds__(256, 2) void knn_kernel(const float* __restrict__ pos,
                                                     const int* __restrict__ edges) {
    __shared__ __align__(16) float s_pos[CT*PST];
    __shared__ __align__(16) float s_q[QB*PST];
    __shared__ float s_pn2[CT];

    const int t    = threadIdx.x;
    const int lane = t & 15;
    const int qp   = t >> 4;
    const int h    = blockIdx.y;
    const int part = blockIdx.z;
    const int qbase = blockIdx.x * QB;

    // stage the 32 query vectors (candidate-major style rows)
    for (int i = t; i < QB*16; i += 256) {
        int qi = i >> 4, f = i & 15;
        int node = edges[qbase + qi];
        float4 v = ((const float4*)(pos + ((size_t)node*HH + h)*DD))[f];
        *(float4*)&s_q[qi*PST + 4*f] = v;
    }
    __syncthreads();

    const float INF = __int_as_float(0x7f800000);
    float lvA[KK+1]; int liA[KK+1];
    float lvB[KK+1]; int liB[KK+1];
#pragma unroll
    for (int i = 0; i <= KK; i++) {
        lvA[i] = INF; liA[i] = 0x7fffffff;
        lvB[i] = INF; liB[i] = 0x7fffffff;
    }

    for (int tile = 0; tile < SPAN/CT; tile++) {
        const int n0 = part*SPAN + tile*CT;

        // ---- stage: pn2 + candidate tile, candidate-major, coalesced ----
        if (t < CT) s_pn2[t] = g_pn2[h*NN + n0 + t];
#pragma unroll
        for (int r = 0; r < (CT*16)/256; r++) {
            int idx = t + 256*r;
            int c = idx >> 4, f = idx & 15;
            float4 v = ((const float4*)(pos + ((size_t)(n0+c)*HH + h)*DD))[f];
            *(float4*)&s_pos[c*PST + 4*f] = v;
        }
        __syncthreads();

        // ---- 2 queries x 8 candidates, f32x2 over d pairs ----
        ull acc[16];
#pragma unroll
        for (int i = 0; i < 16; i++) acc[i] = 0ull;

        const float* qA = &s_q[(2*qp)*PST];
        const float* qB = &s_q[(2*qp+1)*PST];

#pragma unroll
        for (int ch = 0; ch < DD/4; ch++) {
            ulonglong2 qa = *(const ulonglong2*)&qA[4*ch];
            ulonglong2 qb = *(const ulonglong2*)&qB[4*ch];
#pragma unroll
            for (int j = 0; j < 8; j++) {
                ulonglong2 cv = *(const ulonglong2*)&s_pos[(lane + 16*j)*PST + 4*ch];
                FMA2(acc[j],   qa.x, cv.x);
                FMA2(acc[j],   qa.y, cv.y);
                FMA2(acc[8+j], qb.x, cv.x);
                FMA2(acc[8+j], qb.y, cv.y);
            }
        }

        // ---- scores + top-9 insertion (both queries) ----
#pragma unroll
        for (int j = 0; j < 8; j++) {
            int c = lane + 16*j;
            int idx = n0 + c;
            float p2 = s_pn2[c];

            float dA = __uint_as_float((unsigned)acc[j]) +
                       __uint_as_float((unsigned)(acc[j] >> 32));
            float sA = p2 - 2.f*dA;
            if (better(sA, idx, lvA[KK], liA[KK])) {
                lvA[KK] = sA; liA[KK] = idx;
#pragma unroll
                for (int i = KK; i > 0; i--)
                    if (better(lvA[i], liA[i], lvA[i-1], liA[i-1])) {
                        float tv = lvA[i]; lvA[i] = lvA[i-1]; lvA[i-1] = tv;
                        int   ti = liA[i]; liA[i] = liA[i-1]; liA[i-1] = ti;
                    }
            }

            float dB = __uint_as_float((unsigned)acc[8+j]) +
                       __uint_as_float((unsigned)(acc[8+j] >> 32));
            float sB = p2 - 2.f*dB;
            if (better(sB, idx, lvB[KK], liB[KK])) {
                lvB[KK] = sB; liB[KK] = idx;
#pragma unroll
                for (int i = KK; i > 0; i--)
                    if (better(lvB[i], liB[i], lvB[i-1], liB[i-1])) {
                        float tv = lvB[i]; lvB[i] = lvB[i-1]; lvB[i-1] = tv;
                        int   ti = liB[i]; liB[i] = liB[i-1]; liB[i-1] = ti;
                    }
            }
        }
        __syncthreads();
    }

    // ---- 16-lane merge per query, write partition top-9 ----
    const int qA_glob = qbase + 2*qp;
    const int qB_glob = qA_glob + 1;

#pragma unroll
    for (int which = 0; which < 2; which++) {
        float* lv = which ? lvB : lvA;
        int*   li = which ? liB : liA;
        int qg = which ? qB_glob : qA_glob;
        long base = ((long)(part*NQ + qg)*HH + h)*(KK+1);
        for (int r = 0; r <= KK; r++) {
            float v = lv[0]; int i = li[0];
            float bv = v;   int bi = i;
#pragma unroll
            for (int o = 1; o < 16; o <<= 1) {
                float ov = __shfl_xor_sync(0xffffffffu, bv, o);
                int   oi = __shfl_xor_sync(0xffffffffu, bi, o);
                if (better(ov, oi, bv, bi)) { bv = ov; bi = oi; }
            }
            if (v == bv && i == bi) {   // this lane's head won: pop
#pragma unroll
                for (int j = 0; j < KK; j++) { lv[j] = lv[j+1]; li[j] = li[j+1]; }
                lv[KK] = __int_as_float(0x7f800000); li[KK] = 0x7fffffff;
            }
            if (lane == 0) { g_pv[base + r] = bv; g_pi[base + r] = bi; }
        }
    }
}

// ---------------------------------------------------------------- kernel 2b
// Merge NPART partial top-9 lists -> top-8 excluding self (= global min).
__global__ __launch_bounds__(256) void merge_kernel() {
    int id = blockIdx.x*256 + threadIdx.x;   // q*HH + h
    if (id >= NQ*HH) return;
    int q = id / HH, h = id % HH;

    float v[NPART*(KK+1)]; int ix[NPART*(KK+1)];
#pragma unroll
    for (int p = 0; p < NPART; p++) {
        long base = ((long)(p*NQ + q)*HH + h)*(KK+1);
#pragma unroll
        for (int r = 0; r <= KK; r++) {
            v[p*(KK+1)+r]  = g_pv[base + r];
            ix[p*(KK+1)+r] = g_pi[base + r];
        }
    }
    for (int r = 0; r <= KK; r++) {
        int best = 0;
#pragma unroll
        for (int j = 1; j < NPART*(KK+1); j++)
            if (better(v[j], ix[j], v[best], ix[best])) best = j;
        if (r >= 1) g_knn[id*KK + (r-1)] = ix[best];
        v[best] = __int_as_float(0x7f800000); ix[best] = 0x7fffffff;
    }
}

// ---------------------------------------------------------------- kernel 3
__global__ __launch_bounds__(64) void epi_kernel(const float* __restrict__ pos,
                                                 const float* __restrict__ grads,
                                                 const float* __restrict__ adj,
                                                 const float* __restrict__ lw,
                                                 const int* __restrict__ edges,
                                                 float* __restrict__ out) {
    __shared__ float sd[HH*16];
    __shared__ float sl[HH*16];
    __shared__ float sh[HH];

    int b = blockIdx.x, t = threadIdx.x;
    int side = t >> 5;
    int h = (t >> 3) & 3;
    int k = t & 7;

    int sb = edges[b], db = edges[BB + b];
    int qn = side ? db : sb;
    int gn = side ? sb : db;
    int q  = side ? (BB + b) : b;
    int nb = g_knn[(q*HH + h)*KK + k];

    const float4* qp = (const float4*)(pos   + ((size_t)qn*HH + h)*DD);
    const float4* np = (const float4*)(pos   + ((size_t)nb*HH + h)*DD);
    const float4* gp = (const float4*)(grads + ((size_t)gn*HH + h)*DD);

    float ss = 0.f, cc = 0.f;
#pragma unroll
    for (int i = 0; i < DD/4; i++) {
        float4 a = qp[i], c = np[i], g4 = gp[i];
        float d0 = a.x - c.x, d1 = a.y - c.y, d2 = a.z - c.z, d3 = a.w - c.w;
        ss += d0*d0 + d1*d1 + d2*d2 + d3*d3;
        cc += d0*g4.x + d1*g4.y + d2*g4.z + d3*g4.w;
    }
    float dist = sqrtf(ss);
    float adjv = side ? adj[(size_t)sb*NN + nb] : adj[(size_t)nb*NN + db];
    float logit = lw[0]*adjv + cc;

    int slot = h*16 + side*8 + k;
    sd[slot] = dist;
    sl[slot] = logit;
    __syncthreads();

    if (t < HH) {
        float mind = 1.0f;
#pragma unroll
        for (int j = 0; j < 16; j++) mind = fminf(mind, sd[t*16 + j]);
        float num = 0.f;
        float den = 8.f * expf(mind - 1.0f);
#pragma unroll
        for (int j = 0; j < 16; j++) {
            float e = expf(mind - sd[t*16 + j]);
            den += e;
            num += e * sl[t*16 + j];
        }
        sh[t] = num / den;
    }
    __syncthreads();
    if (t == 0) {
        float s = 0.25f * (sh[0] + sh[1] + sh[2] + sh[3]);
        out[b] = 1.f / (1.f + expf(-s));
    }
}

// ---------------------------------------------------------------- launch
extern "C" void kernel_launch(void* const* d_in, const int* in_sizes, int n_in,
                              void* d_out, int out_size) {
    const float* pos   = (const float*)d_in[0];
    const float* grads = (const float*)d_in[1];
    const float* adj   = (const float*)d_in[2];
    const float* lw    = (const float*)d_in[3];
    const int*   edges = (const int*)  d_in[4];
    float* out = (float*)d_out;

    pn2_kernel<<<(NN*HH)/256, 256>>>(pos);
    knn_kernel<<<dim3(NQ/QB, HH, NPART), 256>>>(pos, edges);
    merge_kernel<<<(NQ*HH + 255)/256, 256>>>();
    epi_kernel<<<BB, 64>>>(pos, grads, adj, lw, edges, out);
}